// round 5
// baseline (speedup 1.0000x reference)
#include <cuda_runtime.h>
#include <math.h>

// Problem constants
#define B_  2
#define L_  2048
#define C_  1024
#define H_  16
#define D_  64
#define BL_ (B_*L_)      // 4096
#define C3_ (3*C_)       // 3072

// ---------------- scratch (no allocation allowed) ----------------
__device__ float g_qkv[(size_t)BL_ * C3_];        // 50 MB
__device__ float g_q[(size_t)B_*H_*L_*D_];        // 16 MB  [B,H,L,D]
__device__ float g_k[(size_t)B_*H_*L_*D_];        // 16 MB
__device__ float g_v[(size_t)B_*H_*L_*D_];        // 16 MB
__device__ float g_att[(size_t)BL_ * C_];         // 16 MB  [B,L,C]

// =================================================================
// Kernel 1/4: C[m,n] = sum_k A[m,k]*Bw[n,k] + bias[n]
// A: [M,K] row-major, Bw: [N,K] row-major (i.e. X @ W^T + b)
// 128x128 tile, BK=16, 256 threads, 8x8 per-thread microtile.
// =================================================================
__global__ __launch_bounds__(256) void sgemm_nt(
    const float* __restrict__ A, const float* __restrict__ Bw,
    const float* __restrict__ bias, float* __restrict__ Co,
    int M, int N, int K)
{
    __shared__ float As[16][132];
    __shared__ float Bs[16][132];
    const int tid = threadIdx.x;
    const int ty = tid >> 4;      // 0..15
    const int tx = tid & 15;      // 0..15
    const int row0 = blockIdx.y << 7;
    const int col0 = blockIdx.x << 7;

    const float* Aptr = A  + (size_t)row0 * K;
    const float* Bptr = Bw + (size_t)col0 * K;

    float acc[8][8];
#pragma unroll
    for (int i = 0; i < 8; i++)
#pragma unroll
        for (int j = 0; j < 8; j++) acc[i][j] = 0.f;

    for (int k0 = 0; k0 < K; k0 += 16) {
#pragma unroll
        for (int q = 0; q < 2; q++) {
            int lin = tid + q * 256;          // 0..511 float4 slots
            int r   = lin >> 2;               // 0..127
            int kk  = (lin & 3) << 2;         // 0,4,8,12
            float4 va = *reinterpret_cast<const float4*>(Aptr + (size_t)r * K + k0 + kk);
            As[kk + 0][r] = va.x; As[kk + 1][r] = va.y;
            As[kk + 2][r] = va.z; As[kk + 3][r] = va.w;
            float4 vb = *reinterpret_cast<const float4*>(Bptr + (size_t)r * K + k0 + kk);
            Bs[kk + 0][r] = vb.x; Bs[kk + 1][r] = vb.y;
            Bs[kk + 2][r] = vb.z; Bs[kk + 3][r] = vb.w;
        }
        __syncthreads();
#pragma unroll
        for (int k = 0; k < 16; k++) {
            float4 a0 = *reinterpret_cast<const float4*>(&As[k][ty * 8]);
            float4 a1 = *reinterpret_cast<const float4*>(&As[k][ty * 8 + 4]);
            float4 b0 = *reinterpret_cast<const float4*>(&Bs[k][tx * 8]);
            float4 b1 = *reinterpret_cast<const float4*>(&Bs[k][tx * 8 + 4]);
            float av[8] = {a0.x, a0.y, a0.z, a0.w, a1.x, a1.y, a1.z, a1.w};
            float bv[8] = {b0.x, b0.y, b0.z, b0.w, b1.x, b1.y, b1.z, b1.w};
#pragma unroll
            for (int i = 0; i < 8; i++)
#pragma unroll
                for (int j = 0; j < 8; j++)
                    acc[i][j] += av[i] * bv[j];
        }
        __syncthreads();
    }

#pragma unroll
    for (int i = 0; i < 8; i++) {
        int r = row0 + ty * 8 + i;
#pragma unroll
        for (int j = 0; j < 8; j += 4) {
            int cidx = col0 + tx * 8 + j;
            float4 o;
            o.x = acc[i][j + 0] + bias[cidx + 0];
            o.y = acc[i][j + 1] + bias[cidx + 1];
            o.z = acc[i][j + 2] + bias[cidx + 2];
            o.w = acc[i][j + 3] + bias[cidx + 3];
            *reinterpret_cast<float4*>(Co + (size_t)r * N + cidx) = o;
        }
    }
}

// =================================================================
// Kernel 2: RoPE + QK-RMSNorm + split to [B,H,L,D]. One warp per (b,l,h).
// Lane j handles the pair (2j, 2j+1) of the 64-wide head dim.
// =================================================================
__global__ __launch_bounds__(256) void rope_rms_split(
    const float* __restrict__ qkv,
    const float* __restrict__ q_gamma, const float* __restrict__ k_gamma,
    float* __restrict__ gq, float* __restrict__ gk, float* __restrict__ gv)
{
    int warp = (blockIdx.x * blockDim.x + threadIdx.x) >> 5;
    int lane = threadIdx.x & 31;
    if (warp >= B_ * L_ * H_) return;
    int h  = warp % H_;
    int bl = warp / H_;            // b*L + l
    int l  = bl % L_;
    int b  = bl / L_;

    const float* base = qkv + (size_t)bl * C3_;
    const size_t orow = (((size_t)(b * H_ + h)) * L_ + l) * D_;

    // inv_freq = 10000^(-lane/32): precise exp2f; angle up to ~2047, use precise sincosf
    float inv_freq = exp2f((float)lane * (-13.287712379549449f / 32.0f));
    float ang = (float)l * inv_freq;
    float s, c;
    sincosf(ang, &s, &c);

    // ---- Q ----
    {
        float t1 = base[0 * C_ + h * D_ + 2 * lane];
        float t2 = base[0 * C_ + h * D_ + 2 * lane + 1];
        float r1 = t1 * c - t2 * s;
        float r2 = t1 * s + t2 * c;
        float ss = r1 * r1 + r2 * r2;
#pragma unroll
        for (int off = 16; off > 0; off >>= 1)
            ss += __shfl_xor_sync(0xffffffffu, ss, off);
        float inv = rsqrtf(ss * (1.0f / 64.0f) + 1e-6f);
        gq[orow + 2 * lane]     = r1 * inv * q_gamma[h * D_ + 2 * lane];
        gq[orow + 2 * lane + 1] = r2 * inv * q_gamma[h * D_ + 2 * lane + 1];
    }
    // ---- K ----
    {
        float t1 = base[1 * C_ + h * D_ + 2 * lane];
        float t2 = base[1 * C_ + h * D_ + 2 * lane + 1];
        float r1 = t1 * c - t2 * s;
        float r2 = t1 * s + t2 * c;
        float ss = r1 * r1 + r2 * r2;
#pragma unroll
        for (int off = 16; off > 0; off >>= 1)
            ss += __shfl_xor_sync(0xffffffffu, ss, off);
        float inv = rsqrtf(ss * (1.0f / 64.0f) + 1e-6f);
        gk[orow + 2 * lane]     = r1 * inv * k_gamma[h * D_ + 2 * lane];
        gk[orow + 2 * lane + 1] = r2 * inv * k_gamma[h * D_ + 2 * lane + 1];
    }
    // ---- V (plain copy) ----
    gv[orow + 2 * lane]     = base[2 * C_ + h * D_ + 2 * lane];
    gv[orow + 2 * lane + 1] = base[2 * C_ + h * D_ + 2 * lane + 1];
}

// =================================================================
// Kernel 3: flash attention, fp32, 64x64 tiles, online softmax.
// Grid: (L/64, H, B). 256 threads = 16x16 grid, 4x4 microtiles.
// Smem layouts (LDP=68 to keep float4 alignment + conflict-free):
//   Qs[k][r] (transposed, pre-scaled by 1/8), Ks[k][c] (transposed),
//   Vs[kk][c] (natural), Ps[kk][r] (transposed P).
// =================================================================
#define LDP 68
#define ATTN_SMEM (4 * 64 * LDP * (int)sizeof(float))   // 69632 B

__global__ __launch_bounds__(256) void attn_kernel(
    const float* __restrict__ gq, const float* __restrict__ gk,
    const float* __restrict__ gv, float* __restrict__ gout)
{
    extern __shared__ float sm[];
    float* Qs = sm;
    float* Ks = sm + 64 * LDP;
    float* Vs = sm + 2 * 64 * LDP;
    float* Ps = sm + 3 * 64 * LDP;

    const int tid = threadIdx.x;
    const int ty = tid >> 4;      // 0..15  -> rows ty*4..ty*4+3
    const int tx = tid & 15;      // 0..15  -> cols tx*4..tx*4+3
    const int qt = blockIdx.x, h = blockIdx.y, b = blockIdx.z;

    const size_t base = ((size_t)(b * H_ + h)) * L_ * D_;
    const float* Q  = gq + base + (size_t)qt * 64 * D_;
    const float* Kp = gk + base;
    const float* Vp = gv + base;

    // Load Q tile transposed, pre-scaled by 1/sqrt(64)=0.125 (exact pow2)
#pragma unroll
    for (int q = 0; q < 4; q++) {
        int lin4 = tid + q * 256;        // 0..1023 float4 slots
        int r    = lin4 >> 4;            // 0..63
        int kk   = (lin4 & 15) << 2;     // 0..60
        float4 v = *reinterpret_cast<const float4*>(Q + (size_t)r * D_ + kk);
        Qs[(kk + 0) * LDP + r] = v.x * 0.125f;
        Qs[(kk + 1) * LDP + r] = v.y * 0.125f;
        Qs[(kk + 2) * LDP + r] = v.z * 0.125f;
        Qs[(kk + 3) * LDP + r] = v.w * 0.125f;
    }

    float o[4][4];
#pragma unroll
    for (int i = 0; i < 4; i++)
#pragma unroll
        for (int j = 0; j < 4; j++) o[i][j] = 0.f;
    float mrow[4] = {-INFINITY, -INFINITY, -INFINITY, -INFINITY};
    float lrow[4] = {0.f, 0.f, 0.f, 0.f};

    for (int kt = 0; kt < L_ / 64; kt++) {
        __syncthreads();   // previous tile's Ks/Vs/Ps consumed; Q ready (1st iter)
        // Load K (transposed) + V (natural)
#pragma unroll
        for (int q = 0; q < 4; q++) {
            int lin4 = tid + q * 256;
            int c    = lin4 >> 4;
            int kk   = (lin4 & 15) << 2;
            const float* krow = Kp + (size_t)(kt * 64 + c) * D_ + kk;
            float4 kv = *reinterpret_cast<const float4*>(krow);
            Ks[(kk + 0) * LDP + c] = kv.x;
            Ks[(kk + 1) * LDP + c] = kv.y;
            Ks[(kk + 2) * LDP + c] = kv.z;
            Ks[(kk + 3) * LDP + c] = kv.w;
            const float* vrow = Vp + (size_t)(kt * 64 + c) * D_ + kk;
            *reinterpret_cast<float4*>(&Vs[c * LDP + kk]) =
                *reinterpret_cast<const float4*>(vrow);
        }
        __syncthreads();

        // S = (Q*scale) K^T  -- 4x4 microtile
        float s[4][4];
#pragma unroll
        for (int i = 0; i < 4; i++)
#pragma unroll
            for (int j = 0; j < 4; j++) s[i][j] = 0.f;
#pragma unroll 8
        for (int k = 0; k < 64; k++) {
            float4 qa4 = *reinterpret_cast<const float4*>(&Qs[k * LDP + ty * 4]);
            float4 kb4 = *reinterpret_cast<const float4*>(&Ks[k * LDP + tx * 4]);
            float qa[4] = {qa4.x, qa4.y, qa4.z, qa4.w};
            float kb[4] = {kb4.x, kb4.y, kb4.z, kb4.w};
#pragma unroll
            for (int i = 0; i < 4; i++)
#pragma unroll
                for (int j = 0; j < 4; j++)
                    s[i][j] += qa[i] * kb[j];
        }

        // Online softmax (row stats replicated across the 16 tx lanes)
        float mnew[4], corr[4];
#pragma unroll
        for (int i = 0; i < 4; i++) {
            float rm = fmaxf(fmaxf(s[i][0], s[i][1]), fmaxf(s[i][2], s[i][3]));
            rm = fmaxf(rm, __shfl_xor_sync(0xffffffffu, rm, 1, 16));
            rm = fmaxf(rm, __shfl_xor_sync(0xffffffffu, rm, 2, 16));
            rm = fmaxf(rm, __shfl_xor_sync(0xffffffffu, rm, 4, 16));
            rm = fmaxf(rm, __shfl_xor_sync(0xffffffffu, rm, 8, 16));
            mnew[i] = fmaxf(mrow[i], rm);
            corr[i] = __expf(mrow[i] - mnew[i]);   // exp(-inf)=0 on first tile
            mrow[i] = mnew[i];
        }
#pragma unroll
        for (int i = 0; i < 4; i++) {
            float ls = 0.f;
#pragma unroll
            for (int j = 0; j < 4; j++) {
                float p = __expf(s[i][j] - mnew[i]);
                s[i][j] = p;
                ls += p;
            }
            ls += __shfl_xor_sync(0xffffffffu, ls, 1, 16);
            ls += __shfl_xor_sync(0xffffffffu, ls, 2, 16);
            ls += __shfl_xor_sync(0xffffffffu, ls, 4, 16);
            ls += __shfl_xor_sync(0xffffffffu, ls, 8, 16);
            lrow[i] = lrow[i] * corr[i] + ls;
            o[i][0] *= corr[i]; o[i][1] *= corr[i];
            o[i][2] *= corr[i]; o[i][3] *= corr[i];
        }

        // Store P transposed: Ps[key][row]
#pragma unroll
        for (int j = 0; j < 4; j++)
#pragma unroll
            for (int i = 0; i < 4; i++)
                Ps[(tx * 4 + j) * LDP + ty * 4 + i] = s[i][j];
        __syncthreads();

        // O += P V
#pragma unroll 8
        for (int kk = 0; kk < 64; kk++) {
            float4 pa4 = *reinterpret_cast<const float4*>(&Ps[kk * LDP + ty * 4]);
            float4 vb4 = *reinterpret_cast<const float4*>(&Vs[kk * LDP + tx * 4]);
            float pa[4] = {pa4.x, pa4.y, pa4.z, pa4.w};
            float vb[4] = {vb4.x, vb4.y, vb4.z, vb4.w};
#pragma unroll
            for (int i = 0; i < 4; i++)
#pragma unroll
                for (int j = 0; j < 4; j++)
                    o[i][j] += pa[i] * vb[j];
        }
    }

    // Epilogue: normalize, write to [B, L, C] layout
#pragma unroll
    for (int i = 0; i < 4; i++) {
        float inv = 1.0f / lrow[i];
        int r = qt * 64 + ty * 4 + i;
        float4 ov;
        ov.x = o[i][0] * inv; ov.y = o[i][1] * inv;
        ov.z = o[i][2] * inv; ov.w = o[i][3] * inv;
        *reinterpret_cast<float4*>(gout + ((size_t)(b * L_ + r)) * C_ + h * D_ + tx * 4) = ov;
    }
}

// =================================================================
// Host launcher
// =================================================================
extern "C" void kernel_launch(void* const* d_in, const int* in_sizes, int n_in,
                              void* d_out, int out_size)
{
    const float* x       = (const float*)d_in[0];
    const float* w_qkv   = (const float*)d_in[1];
    const float* b_qkv   = (const float*)d_in[2];
    const float* w_out   = (const float*)d_in[3];
    const float* b_out   = (const float*)d_in[4];
    const float* q_gamma = (const float*)d_in[5];
    const float* k_gamma = (const float*)d_in[6];
    float* out = (float*)d_out;
    (void)in_sizes; (void)n_in; (void)out_size;

    float *qkv, *q, *k, *v, *att;
    cudaGetSymbolAddress((void**)&qkv, g_qkv);
    cudaGetSymbolAddress((void**)&q,   g_q);
    cudaGetSymbolAddress((void**)&k,   g_k);
    cudaGetSymbolAddress((void**)&v,   g_v);
    cudaGetSymbolAddress((void**)&att, g_att);

    cudaFuncSetAttribute(attn_kernel,
                         cudaFuncAttributeMaxDynamicSharedMemorySize, ATTN_SMEM);

    // 1) QKV projection: [4096,3072] = x @ w_qkv^T + b_qkv
    sgemm_nt<<<dim3(C3_ / 128, BL_ / 128), 256>>>(x, w_qkv, b_qkv, qkv,
                                                  BL_, C3_, C_);
    // 2) RoPE + RMS + split into [B,H,L,D]
    rope_rms_split<<<(B_ * L_ * H_ * 32) / 256, 256>>>(qkv, q_gamma, k_gamma,
                                                       q, k, v);
    // 3) Flash attention -> [B,L,C]
    attn_kernel<<<dim3(L_ / 64, H_, B_), 256, ATTN_SMEM>>>(q, k, v, att);
    // 4) Output projection: out = att @ w_out^T + b_out
    sgemm_nt<<<dim3(C_ / 128, BL_ / 128), 256>>>(att, w_out, b_out, out,
                                                 BL_, C_, C_);
}

// round 8
// speedup vs baseline: 1.3322x; 1.3322x over previous
#include <cuda_runtime.h>
#include <cuda_bf16.h>
#include <math.h>
#include <stdint.h>

// Problem constants
#define B_  2
#define L_  2048
#define C_  1024
#define H_  16
#define D_  64
#define BL_ (B_*L_)      // 4096
#define C3_ (3*C_)       // 3072
#define K_  1024         // inner dim of both dense GEMMs

// ---------------- scratch (no allocation allowed) ----------------
__device__ float g_qkv[(size_t)BL_ * C3_];
__device__ float g_q[(size_t)B_*H_*L_*D_];
__device__ float g_k[(size_t)B_*H_*L_*D_];
__device__ float g_v[(size_t)B_*H_*L_*D_];
__device__ float g_att[(size_t)BL_ * C_];

__device__ __nv_bfloat16 g_x_hi [(size_t)BL_*C_];
__device__ __nv_bfloat16 g_x_lo [(size_t)BL_*C_];
__device__ __nv_bfloat16 g_wq_hi[(size_t)C3_*C_];
__device__ __nv_bfloat16 g_wq_lo[(size_t)C3_*C_];
__device__ __nv_bfloat16 g_wo_hi[(size_t)C_*C_];
__device__ __nv_bfloat16 g_wo_lo[(size_t)C_*C_];
__device__ __nv_bfloat16 g_at_hi[(size_t)BL_*C_];
__device__ __nv_bfloat16 g_at_lo[(size_t)BL_*C_];

// =================================================================
// helpers
// =================================================================
__device__ __forceinline__ uint32_t smem_u32(const void* p) {
    uint32_t a;
    asm("{ .reg .u64 t; cvta.to.shared.u64 t, %1; cvt.u32.u64 %0, t; }"
        : "=r"(a) : "l"(p));
    return a;
}
__device__ __forceinline__ void cpasync16(uint32_t dst, const void* src) {
    asm volatile("cp.async.cg.shared.global [%0], [%1], 16;"
                 :: "r"(dst), "l"(src));
}
__device__ __forceinline__ void ldm4(uint32_t* r, uint32_t addr) {
    asm volatile("ldmatrix.sync.aligned.m8n8.x4.shared.b16 {%0,%1,%2,%3}, [%4];"
                 : "=r"(r[0]), "=r"(r[1]), "=r"(r[2]), "=r"(r[3]) : "r"(addr));
}
__device__ __forceinline__ void mma_bf16(float* c, const uint32_t* a,
                                         const uint32_t* b) {
    asm volatile(
        "mma.sync.aligned.m16n8k16.row.col.f32.bf16.bf16.f32 "
        "{%0,%1,%2,%3}, {%4,%5,%6,%7}, {%8,%9}, {%0,%1,%2,%3};"
        : "+f"(c[0]), "+f"(c[1]), "+f"(c[2]), "+f"(c[3])
        : "r"(a[0]), "r"(a[1]), "r"(a[2]), "r"(a[3]), "r"(b[0]), "r"(b[1]));
}

// =================================================================
// Split-bf16 mma.sync GEMM: C[m,n] = sum_k A[m,k]*B[n,k] + bias[n]
// A:[M,K] bf16 hi/lo, B:[Nt,K] bf16 hi/lo (both K-contiguous), C fp32.
// CTA tile 128x128, BK=32, double-buffered cp.async.
// Smem per stage: Ah | Al | Bh | Bl, each 128 rows x pitch 40 bf16 (80B).
// =================================================================
#define PITCH_B   80                 // bytes per smem row
#define MAT_BYTES (128 * PITCH_B)    // 10240
#define STG_BYTES (4 * MAT_BYTES)    // 40960
#define GEMM_DSMEM (2 * STG_BYTES)   // 81920

__global__ __launch_bounds__(256)
void gemm_mma(const __nv_bfloat16* __restrict__ Ahi,
              const __nv_bfloat16* __restrict__ Alo,
              const __nv_bfloat16* __restrict__ Bhi,
              const __nv_bfloat16* __restrict__ Blo,
              const float* __restrict__ bias,
              float* __restrict__ Cout, int Nt)
{
    extern __shared__ char dsm[];
    const uint32_t sb = smem_u32(dsm);

    const int tid  = threadIdx.x;
    const int wid  = tid >> 5;
    const int lane = tid & 31;
    const int wm   = wid >> 1;        // 0..3 -> 32-row slab
    const int wn   = wid & 1;         // 0..1 -> 64-col slab
    const int row0 = blockIdx.y << 7;
    const int col0 = blockIdx.x << 7;

    auto load_chunk = [&](int c, int s) {
        const uint32_t st = sb + s * STG_BYTES;
        const int kb = c * 32;
#pragma unroll
        for (int t = 0; t < 2; t++) {       // A: 128 rows x 32 bf16
            int lin = tid + t * 256;        // 0..511
            int r = lin >> 2, q = lin & 3;
            uint32_t so = (uint32_t)(r * PITCH_B + q * 16);
            size_t go = (size_t)(row0 + r) * K_ + kb + q * 8;
            cpasync16(st + so,             Ahi + go);
            cpasync16(st + MAT_BYTES + so, Alo + go);
        }
#pragma unroll
        for (int t = 0; t < 2; t++) {       // B: 128 rows x 32 bf16
            int lin = tid + t * 256;
            int r = lin >> 2, q = lin & 3;
            uint32_t so = (uint32_t)(r * PITCH_B + q * 16);
            size_t go = (size_t)(col0 + r) * K_ + kb + q * 8;
            cpasync16(st + 2 * MAT_BYTES + so, Bhi + go);
            cpasync16(st + 3 * MAT_BYTES + so, Blo + go);
        }
        asm volatile("cp.async.commit_group;" ::: "memory");
    };

    float acc[2][8][4];
#pragma unroll
    for (int i = 0; i < 2; i++)
#pragma unroll
        for (int j = 0; j < 8; j++)
#pragma unroll
            for (int t = 0; t < 4; t++) acc[i][j][t] = 0.f;

    load_chunk(0, 0);
    load_chunk(1, 1);

    const int NCH = K_ / 32;          // 32
    // ldmatrix per-lane addressing.
    // A fragment (a0=r0-7/k0-7, a1=r8-15/k0-7, a2=r0-7/k8-15, a3=r8-15/k8-15):
    //   lanes 0-15 -> rows 0-15 at k+0; lanes 16-31 -> rows 0-15 at k+8
    const int rlA = lane & 15;
    const int csA = (lane >> 4) << 3;       // 0 or 8 (elements)
    // B fragment (b0=n0-7/k0-7, b1=n0-7/k8-15; second 8-wide n tile in r2,r3):
    //   lanes 0-7 -> n0-7 k+0; 8-15 -> n0-7 k+8; 16-23 -> n8-15 k+0; 24-31 -> n8-15 k+8
    const int rlB = (lane & 7) + ((lane >> 4) << 3);
    const int csB = lane & 8;               // 0 or 8 (elements)

    for (int c = 0; c < NCH; c++) {
        const int s = c & 1;
        if (c == NCH - 1)
            asm volatile("cp.async.wait_group 0;" ::: "memory");
        else
            asm volatile("cp.async.wait_group 1;" ::: "memory");
        __syncthreads();

        const uint32_t st = sb + s * STG_BYTES;
#pragma unroll
        for (int kk = 0; kk < 32; kk += 16) {
            uint32_t aH[2][4], aL[2][4];
#pragma unroll
            for (int mt = 0; mt < 2; mt++) {
                uint32_t ad = st + (uint32_t)((wm * 32 + mt * 16 + rlA) * PITCH_B
                                              + (kk + csA) * 2);
                ldm4(aH[mt], ad);
                ldm4(aL[mt], ad + MAT_BYTES);
            }
#pragma unroll
            for (int ntp = 0; ntp < 4; ntp++) {
                uint32_t bd = st + 2 * MAT_BYTES
                            + (uint32_t)((wn * 64 + ntp * 16 + rlB) * PITCH_B
                                         + (kk + csB) * 2);
                uint32_t bH[4], bL[4];
                ldm4(bH, bd);
                ldm4(bL, bd + MAT_BYTES);
#pragma unroll
                for (int mt = 0; mt < 2; mt++) {
                    mma_bf16(acc[mt][2 * ntp],     aH[mt], bH);
                    mma_bf16(acc[mt][2 * ntp],     aH[mt], bL);
                    mma_bf16(acc[mt][2 * ntp],     aL[mt], bH);
                    mma_bf16(acc[mt][2 * ntp + 1], aH[mt], bH + 2);
                    mma_bf16(acc[mt][2 * ntp + 1], aH[mt], bL + 2);
                    mma_bf16(acc[mt][2 * ntp + 1], aL[mt], bH + 2);
                }
            }
        }
        __syncthreads();
        if (c + 2 < NCH) load_chunk(c + 2, s);
    }

    // Epilogue: c0,c1 -> (row, col..col+1); c2,c3 -> (row+8, ...)
#pragma unroll
    for (int mt = 0; mt < 2; mt++) {
#pragma unroll
        for (int nt = 0; nt < 8; nt++) {
            int row = row0 + wm * 32 + mt * 16 + (lane >> 2);
            int col = col0 + wn * 64 + nt * 8 + (lane & 3) * 2;
            float bx = bias[col], by = bias[col + 1];
            float2 v0 = {acc[mt][nt][0] + bx, acc[mt][nt][1] + by};
            float2 v1 = {acc[mt][nt][2] + bx, acc[mt][nt][3] + by};
            *reinterpret_cast<float2*>(Cout + (size_t)row * Nt + col) = v0;
            *reinterpret_cast<float2*>(Cout + (size_t)(row + 8) * Nt + col) = v1;
        }
    }
}

// =================================================================
// fp32 -> (hi, lo) bf16 split, vectorized
// =================================================================
__global__ __launch_bounds__(256) void split_bf16_k(
    const float4* __restrict__ in, __nv_bfloat162* __restrict__ hi,
    __nv_bfloat162* __restrict__ lo, int n4)
{
    int i = blockIdx.x * blockDim.x + threadIdx.x;
    if (i >= n4) return;
    float4 a = in[i];
    __nv_bfloat16 hx = __float2bfloat16(a.x);
    __nv_bfloat16 hy = __float2bfloat16(a.y);
    __nv_bfloat16 hz = __float2bfloat16(a.z);
    __nv_bfloat16 hw = __float2bfloat16(a.w);
    hi[2 * i]     = __halves2bfloat162(hx, hy);
    hi[2 * i + 1] = __halves2bfloat162(hz, hw);
    __nv_bfloat16 lx = __float2bfloat16(a.x - __bfloat162float(hx));
    __nv_bfloat16 ly = __float2bfloat16(a.y - __bfloat162float(hy));
    __nv_bfloat16 lz = __float2bfloat16(a.z - __bfloat162float(hz));
    __nv_bfloat16 lw = __float2bfloat16(a.w - __bfloat162float(hw));
    lo[2 * i]     = __halves2bfloat162(lx, ly);
    lo[2 * i + 1] = __halves2bfloat162(lz, lw);
}

// =================================================================
// RoPE + QK-RMSNorm + split to [B,H,L,D]. One warp per (b,l,h).
// =================================================================
__global__ __launch_bounds__(256) void rope_rms_split(
    const float* __restrict__ qkv,
    const float* __restrict__ q_gamma, const float* __restrict__ k_gamma,
    float* __restrict__ gq, float* __restrict__ gk, float* __restrict__ gv)
{
    int warp = (blockIdx.x * blockDim.x + threadIdx.x) >> 5;
    int lane = threadIdx.x & 31;
    if (warp >= B_ * L_ * H_) return;
    int h  = warp % H_;
    int bl = warp / H_;
    int l  = bl % L_;
    int b  = bl / L_;

    const float* base = qkv + (size_t)bl * C3_;
    const size_t orow = (((size_t)(b * H_ + h)) * L_ + l) * D_;

    float inv_freq = exp2f((float)lane * (-13.287712379549449f / 32.0f));
    float ang = (float)l * inv_freq;
    float s, c;
    sincosf(ang, &s, &c);

    {
        float t1 = base[0 * C_ + h * D_ + 2 * lane];
        float t2 = base[0 * C_ + h * D_ + 2 * lane + 1];
        float r1 = t1 * c - t2 * s;
        float r2 = t1 * s + t2 * c;
        float ss = r1 * r1 + r2 * r2;
#pragma unroll
        for (int off = 16; off > 0; off >>= 1)
            ss += __shfl_xor_sync(0xffffffffu, ss, off);
        float inv = rsqrtf(ss * (1.0f / 64.0f) + 1e-6f);
        gq[orow + 2 * lane]     = r1 * inv * q_gamma[h * D_ + 2 * lane];
        gq[orow + 2 * lane + 1] = r2 * inv * q_gamma[h * D_ + 2 * lane + 1];
    }
    {
        float t1 = base[1 * C_ + h * D_ + 2 * lane];
        float t2 = base[1 * C_ + h * D_ + 2 * lane + 1];
        float r1 = t1 * c - t2 * s;
        float r2 = t1 * s + t2 * c;
        float ss = r1 * r1 + r2 * r2;
#pragma unroll
        for (int off = 16; off > 0; off >>= 1)
            ss += __shfl_xor_sync(0xffffffffu, ss, off);
        float inv = rsqrtf(ss * (1.0f / 64.0f) + 1e-6f);
        gk[orow + 2 * lane]     = r1 * inv * k_gamma[h * D_ + 2 * lane];
        gk[orow + 2 * lane + 1] = r2 * inv * k_gamma[h * D_ + 2 * lane + 1];
    }
    gv[orow + 2 * lane]     = base[2 * C_ + h * D_ + 2 * lane];
    gv[orow + 2 * lane + 1] = base[2 * C_ + h * D_ + 2 * lane + 1];
}

// =================================================================
// Flash attention, fp32, 64x64 tiles, online softmax. (unchanged)
// =================================================================
#define LDP 68
#define ATTN_SMEM (4 * 64 * LDP * (int)sizeof(float))

__global__ __launch_bounds__(256) void attn_kernel(
    const float* __restrict__ gq, const float* __restrict__ gk,
    const float* __restrict__ gv, float* __restrict__ gout)
{
    extern __shared__ float sm[];
    float* Qs = sm;
    float* Ks = sm + 64 * LDP;
    float* Vs = sm + 2 * 64 * LDP;
    float* Ps = sm + 3 * 64 * LDP;

    const int tid = threadIdx.x;
    const int ty = tid >> 4;
    const int tx = tid & 15;
    const int qt = blockIdx.x, h = blockIdx.y, b = blockIdx.z;

    const size_t base = ((size_t)(b * H_ + h)) * L_ * D_;
    const float* Q  = gq + base + (size_t)qt * 64 * D_;
    const float* Kp = gk + base;
    const float* Vp = gv + base;

#pragma unroll
    for (int q = 0; q < 4; q++) {
        int lin4 = tid + q * 256;
        int r    = lin4 >> 4;
        int kk   = (lin4 & 15) << 2;
        float4 v = *reinterpret_cast<const float4*>(Q + (size_t)r * D_ + kk);
        Qs[(kk + 0) * LDP + r] = v.x * 0.125f;
        Qs[(kk + 1) * LDP + r] = v.y * 0.125f;
        Qs[(kk + 2) * LDP + r] = v.z * 0.125f;
        Qs[(kk + 3) * LDP + r] = v.w * 0.125f;
    }

    float o[4][4];
#pragma unroll
    for (int i = 0; i < 4; i++)
#pragma unroll
        for (int j = 0; j < 4; j++) o[i][j] = 0.f;
    float mrow[4] = {-INFINITY, -INFINITY, -INFINITY, -INFINITY};
    float lrow[4] = {0.f, 0.f, 0.f, 0.f};

    for (int kt = 0; kt < L_ / 64; kt++) {
        __syncthreads();
#pragma unroll
        for (int q = 0; q < 4; q++) {
            int lin4 = tid + q * 256;
            int c    = lin4 >> 4;
            int kk   = (lin4 & 15) << 2;
            const float* krow = Kp + (size_t)(kt * 64 + c) * D_ + kk;
            float4 kv = *reinterpret_cast<const float4*>(krow);
            Ks[(kk + 0) * LDP + c] = kv.x;
            Ks[(kk + 1) * LDP + c] = kv.y;
            Ks[(kk + 2) * LDP + c] = kv.z;
            Ks[(kk + 3) * LDP + c] = kv.w;
            const float* vrow = Vp + (size_t)(kt * 64 + c) * D_ + kk;
            *reinterpret_cast<float4*>(&Vs[c * LDP + kk]) =
                *reinterpret_cast<const float4*>(vrow);
        }
        __syncthreads();

        float s[4][4];
#pragma unroll
        for (int i = 0; i < 4; i++)
#pragma unroll
            for (int j = 0; j < 4; j++) s[i][j] = 0.f;
#pragma unroll 8
        for (int k = 0; k < 64; k++) {
            float4 qa4 = *reinterpret_cast<const float4*>(&Qs[k * LDP + ty * 4]);
            float4 kb4 = *reinterpret_cast<const float4*>(&Ks[k * LDP + tx * 4]);
            float qa[4] = {qa4.x, qa4.y, qa4.z, qa4.w};
            float kb[4] = {kb4.x, kb4.y, kb4.z, kb4.w};
#pragma unroll
            for (int i = 0; i < 4; i++)
#pragma unroll
                for (int j = 0; j < 4; j++)
                    s[i][j] += qa[i] * kb[j];
        }

        float mnew[4], corr[4];
#pragma unroll
        for (int i = 0; i < 4; i++) {
            float rm = fmaxf(fmaxf(s[i][0], s[i][1]), fmaxf(s[i][2], s[i][3]));
            rm = fmaxf(rm, __shfl_xor_sync(0xffffffffu, rm, 1, 16));
            rm = fmaxf(rm, __shfl_xor_sync(0xffffffffu, rm, 2, 16));
            rm = fmaxf(rm, __shfl_xor_sync(0xffffffffu, rm, 4, 16));
            rm = fmaxf(rm, __shfl_xor_sync(0xffffffffu, rm, 8, 16));
            mnew[i] = fmaxf(mrow[i], rm);
            corr[i] = __expf(mrow[i] - mnew[i]);
            mrow[i] = mnew[i];
        }
#pragma unroll
        for (int i = 0; i < 4; i++) {
            float ls = 0.f;
#pragma unroll
            for (int j = 0; j < 4; j++) {
                float p = __expf(s[i][j] - mnew[i]);
                s[i][j] = p;
                ls += p;
            }
            ls += __shfl_xor_sync(0xffffffffu, ls, 1, 16);
            ls += __shfl_xor_sync(0xffffffffu, ls, 2, 16);
            ls += __shfl_xor_sync(0xffffffffu, ls, 4, 16);
            ls += __shfl_xor_sync(0xffffffffu, ls, 8, 16);
            lrow[i] = lrow[i] * corr[i] + ls;
            o[i][0] *= corr[i]; o[i][1] *= corr[i];
            o[i][2] *= corr[i]; o[i][3] *= corr[i];
        }

#pragma unroll
        for (int j = 0; j < 4; j++)
#pragma unroll
            for (int i = 0; i < 4; i++)
                Ps[(tx * 4 + j) * LDP + ty * 4 + i] = s[i][j];
        __syncthreads();

#pragma unroll 8
        for (int kk = 0; kk < 64; kk++) {
            float4 pa4 = *reinterpret_cast<const float4*>(&Ps[kk * LDP + ty * 4]);
            float4 vb4 = *reinterpret_cast<const float4*>(&Vs[kk * LDP + tx * 4]);
            float pa[4] = {pa4.x, pa4.y, pa4.z, pa4.w};
            float vb[4] = {vb4.x, vb4.y, vb4.z, vb4.w};
#pragma unroll
            for (int i = 0; i < 4; i++)
#pragma unroll
                for (int j = 0; j < 4; j++)
                    o[i][j] += pa[i] * vb[j];
        }
    }

#pragma unroll
    for (int i = 0; i < 4; i++) {
        float inv = 1.0f / lrow[i];
        int r = qt * 64 + ty * 4 + i;
        float4 ov;
        ov.x = o[i][0] * inv; ov.y = o[i][1] * inv;
        ov.z = o[i][2] * inv; ov.w = o[i][3] * inv;
        *reinterpret_cast<float4*>(gout + ((size_t)(b * L_ + r)) * C_ + h * D_ + tx * 4) = ov;
    }
}

// =================================================================
// Host launcher
// =================================================================
extern "C" void kernel_launch(void* const* d_in, const int* in_sizes, int n_in,
                              void* d_out, int out_size)
{
    const float* x       = (const float*)d_in[0];
    const float* w_qkv   = (const float*)d_in[1];
    const float* b_qkv   = (const float*)d_in[2];
    const float* w_out   = (const float*)d_in[3];
    const float* b_out   = (const float*)d_in[4];
    const float* q_gamma = (const float*)d_in[5];
    const float* k_gamma = (const float*)d_in[6];
    float* out = (float*)d_out;
    (void)in_sizes; (void)n_in; (void)out_size;

    float *qkv, *q, *k, *v, *att;
    __nv_bfloat16 *xhi, *xlo, *wqhi, *wqlo, *wohi, *wolo, *athi, *atlo;
    cudaGetSymbolAddress((void**)&qkv, g_qkv);
    cudaGetSymbolAddress((void**)&q,   g_q);
    cudaGetSymbolAddress((void**)&k,   g_k);
    cudaGetSymbolAddress((void**)&v,   g_v);
    cudaGetSymbolAddress((void**)&att, g_att);
    cudaGetSymbolAddress((void**)&xhi,  g_x_hi);
    cudaGetSymbolAddress((void**)&xlo,  g_x_lo);
    cudaGetSymbolAddress((void**)&wqhi, g_wq_hi);
    cudaGetSymbolAddress((void**)&wqlo, g_wq_lo);
    cudaGetSymbolAddress((void**)&wohi, g_wo_hi);
    cudaGetSymbolAddress((void**)&wolo, g_wo_lo);
    cudaGetSymbolAddress((void**)&athi, g_at_hi);
    cudaGetSymbolAddress((void**)&atlo, g_at_lo);

    cudaFuncSetAttribute(attn_kernel,
                         cudaFuncAttributeMaxDynamicSharedMemorySize, ATTN_SMEM);
    cudaFuncSetAttribute(gemm_mma,
                         cudaFuncAttributeMaxDynamicSharedMemorySize, GEMM_DSMEM);

    // 0) split inputs/weights to bf16 hi/lo
    int n4;
    n4 = BL_ * C_ / 4;
    split_bf16_k<<<n4 / 256, 256>>>((const float4*)x,
        (__nv_bfloat162*)xhi, (__nv_bfloat162*)xlo, n4);
    n4 = C3_ * C_ / 4;
    split_bf16_k<<<n4 / 256, 256>>>((const float4*)w_qkv,
        (__nv_bfloat162*)wqhi, (__nv_bfloat162*)wqlo, n4);
    n4 = C_ * C_ / 4;
    split_bf16_k<<<n4 / 256, 256>>>((const float4*)w_out,
        (__nv_bfloat162*)wohi, (__nv_bfloat162*)wolo, n4);

    // 1) QKV projection (mma.sync tensor cores): [4096,3072]
    gemm_mma<<<dim3(C3_ / 128, BL_ / 128), 256, GEMM_DSMEM>>>(
        xhi, xlo, wqhi, wqlo, b_qkv, qkv, C3_);

    // 2) RoPE + RMS + split into [B,H,L,D]
    rope_rms_split<<<(B_ * L_ * H_ * 32) / 256, 256>>>(qkv, q_gamma, k_gamma,
                                                       q, k, v);
    // 3) Flash attention -> [B,L,C]
    attn_kernel<<<dim3(L_ / 64, H_, B_), 256, ATTN_SMEM>>>(q, k, v, att);

    // 4) Output projection (mma.sync tensor cores)
    n4 = BL_ * C_ / 4;
    split_bf16_k<<<n4 / 256, 256>>>((const float4*)att,
        (__nv_bfloat162*)athi, (__nv_bfloat162*)atlo, n4);
    gemm_mma<<<dim3(C_ / 128, BL_ / 128), 256, GEMM_DSMEM>>>(
        athi, atlo, wohi, wolo, b_out, out, C_);
}

// round 9
// speedup vs baseline: 2.7729x; 2.0815x over previous
#include <cuda_runtime.h>
#include <cuda_bf16.h>
#include <math.h>
#include <stdint.h>

// Problem constants
#define B_  2
#define L_  2048
#define C_  1024
#define H_  16
#define D_  64
#define BL_ (B_*L_)      // 4096
#define C3_ (3*C_)       // 3072
#define K_  1024         // inner dim of both dense GEMMs

// ---------------- scratch (no allocation allowed) ----------------
__device__ float g_qkv[(size_t)BL_ * C3_];

__device__ __nv_bfloat16 g_x_hi [(size_t)BL_*C_];
__device__ __nv_bfloat16 g_x_lo [(size_t)BL_*C_];
__device__ __nv_bfloat16 g_wq_hi[(size_t)C3_*C_];
__device__ __nv_bfloat16 g_wq_lo[(size_t)C3_*C_];
__device__ __nv_bfloat16 g_wo_hi[(size_t)C_*C_];
__device__ __nv_bfloat16 g_wo_lo[(size_t)C_*C_];
__device__ __nv_bfloat16 g_at_hi[(size_t)BL_*C_];
__device__ __nv_bfloat16 g_at_lo[(size_t)BL_*C_];

__device__ __nv_bfloat16 g_qh [(size_t)B_*H_*L_*D_];
__device__ __nv_bfloat16 g_ql [(size_t)B_*H_*L_*D_];
__device__ __nv_bfloat16 g_kh [(size_t)B_*H_*L_*D_];
__device__ __nv_bfloat16 g_kl [(size_t)B_*H_*L_*D_];
__device__ __nv_bfloat16 g_vth[(size_t)B_*H_*D_*L_];
__device__ __nv_bfloat16 g_vtl[(size_t)B_*H_*D_*L_];

// =================================================================
// helpers
// =================================================================
__device__ __forceinline__ uint32_t smem_u32(const void* p) {
    uint32_t a;
    asm("{ .reg .u64 t; cvta.to.shared.u64 t, %1; cvt.u32.u64 %0, t; }"
        : "=r"(a) : "l"(p));
    return a;
}
__device__ __forceinline__ void cpasync16(uint32_t dst, const void* src) {
    asm volatile("cp.async.cg.shared.global [%0], [%1], 16;"
                 :: "r"(dst), "l"(src));
}
__device__ __forceinline__ void ldm4(uint32_t* r, uint32_t addr) {
    asm volatile("ldmatrix.sync.aligned.m8n8.x4.shared.b16 {%0,%1,%2,%3}, [%4];"
                 : "=r"(r[0]), "=r"(r[1]), "=r"(r[2]), "=r"(r[3]) : "r"(addr));
}
__device__ __forceinline__ void mma_bf16(float* c, const uint32_t* a,
                                         const uint32_t* b) {
    asm volatile(
        "mma.sync.aligned.m16n8k16.row.col.f32.bf16.bf16.f32 "
        "{%0,%1,%2,%3}, {%4,%5,%6,%7}, {%8,%9}, {%0,%1,%2,%3};"
        : "+f"(c[0]), "+f"(c[1]), "+f"(c[2]), "+f"(c[3])
        : "r"(a[0]), "r"(a[1]), "r"(a[2]), "r"(a[3]), "r"(b[0]), "r"(b[1]));
}
// pack two fp32 -> bf16x2 (e -> low half, o -> high half)
__device__ __forceinline__ uint32_t pack_bf16x2(float e, float o) {
    uint32_t r;
    asm("cvt.rn.bf16x2.f32 %0, %1, %2;" : "=r"(r) : "f"(o), "f"(e));
    return r;
}
// truncation split: hi = bf16-truncate(x) (exact in bf16), lo = x - hi
__device__ __forceinline__ void split_pack(float e, float o,
                                           uint32_t& hi, uint32_t& lo) {
    float he = __uint_as_float(__float_as_uint(e) & 0xffff0000u);
    float ho = __uint_as_float(__float_as_uint(o) & 0xffff0000u);
    hi = pack_bf16x2(he, ho);
    lo = pack_bf16x2(e - he, o - ho);
}

// =================================================================
// Split-bf16 mma.sync GEMM (unchanged from R8): C = A B^T + bias
// =================================================================
#define PITCH_B   80
#define MAT_BYTES (128 * PITCH_B)
#define STG_BYTES (4 * MAT_BYTES)
#define GEMM_DSMEM (2 * STG_BYTES)

__global__ __launch_bounds__(256)
void gemm_mma(const __nv_bfloat16* __restrict__ Ahi,
              const __nv_bfloat16* __restrict__ Alo,
              const __nv_bfloat16* __restrict__ Bhi,
              const __nv_bfloat16* __restrict__ Blo,
              const float* __restrict__ bias,
              float* __restrict__ Cout, int Nt)
{
    extern __shared__ char dsm[];
    const uint32_t sb = smem_u32(dsm);

    const int tid  = threadIdx.x;
    const int wid  = tid >> 5;
    const int lane = tid & 31;
    const int wm   = wid >> 1;
    const int wn   = wid & 1;
    const int row0 = blockIdx.y << 7;
    const int col0 = blockIdx.x << 7;

    auto load_chunk = [&](int c, int s) {
        const uint32_t st = sb + s * STG_BYTES;
        const int kb = c * 32;
#pragma unroll
        for (int t = 0; t < 2; t++) {
            int lin = tid + t * 256;
            int r = lin >> 2, q = lin & 3;
            uint32_t so = (uint32_t)(r * PITCH_B + q * 16);
            size_t go = (size_t)(row0 + r) * K_ + kb + q * 8;
            cpasync16(st + so,             Ahi + go);
            cpasync16(st + MAT_BYTES + so, Alo + go);
        }
#pragma unroll
        for (int t = 0; t < 2; t++) {
            int lin = tid + t * 256;
            int r = lin >> 2, q = lin & 3;
            uint32_t so = (uint32_t)(r * PITCH_B + q * 16);
            size_t go = (size_t)(col0 + r) * K_ + kb + q * 8;
            cpasync16(st + 2 * MAT_BYTES + so, Bhi + go);
            cpasync16(st + 3 * MAT_BYTES + so, Blo + go);
        }
        asm volatile("cp.async.commit_group;" ::: "memory");
    };

    float acc[2][8][4];
#pragma unroll
    for (int i = 0; i < 2; i++)
#pragma unroll
        for (int j = 0; j < 8; j++)
#pragma unroll
            for (int t = 0; t < 4; t++) acc[i][j][t] = 0.f;

    load_chunk(0, 0);
    load_chunk(1, 1);

    const int NCH = K_ / 32;
    const int rlA = lane & 15;
    const int csA = (lane >> 4) << 3;
    const int rlB = (lane & 7) + ((lane >> 4) << 3);
    const int csB = lane & 8;

    for (int c = 0; c < NCH; c++) {
        const int s = c & 1;
        if (c == NCH - 1)
            asm volatile("cp.async.wait_group 0;" ::: "memory");
        else
            asm volatile("cp.async.wait_group 1;" ::: "memory");
        __syncthreads();

        const uint32_t st = sb + s * STG_BYTES;
#pragma unroll
        for (int kk = 0; kk < 32; kk += 16) {
            uint32_t aH[2][4], aL[2][4];
#pragma unroll
            for (int mt = 0; mt < 2; mt++) {
                uint32_t ad = st + (uint32_t)((wm * 32 + mt * 16 + rlA) * PITCH_B
                                              + (kk + csA) * 2);
                ldm4(aH[mt], ad);
                ldm4(aL[mt], ad + MAT_BYTES);
            }
#pragma unroll
            for (int ntp = 0; ntp < 4; ntp++) {
                uint32_t bd = st + 2 * MAT_BYTES
                            + (uint32_t)((wn * 64 + ntp * 16 + rlB) * PITCH_B
                                         + (kk + csB) * 2);
                uint32_t bH[4], bL[4];
                ldm4(bH, bd);
                ldm4(bL, bd + MAT_BYTES);
#pragma unroll
                for (int mt = 0; mt < 2; mt++) {
                    mma_bf16(acc[mt][2 * ntp],     aH[mt], bH);
                    mma_bf16(acc[mt][2 * ntp],     aH[mt], bL);
                    mma_bf16(acc[mt][2 * ntp],     aL[mt], bH);
                    mma_bf16(acc[mt][2 * ntp + 1], aH[mt], bH + 2);
                    mma_bf16(acc[mt][2 * ntp + 1], aH[mt], bL + 2);
                    mma_bf16(acc[mt][2 * ntp + 1], aL[mt], bH + 2);
                }
            }
        }
        __syncthreads();
        if (c + 2 < NCH) load_chunk(c + 2, s);
    }

#pragma unroll
    for (int mt = 0; mt < 2; mt++) {
#pragma unroll
        for (int nt = 0; nt < 8; nt++) {
            int row = row0 + wm * 32 + mt * 16 + (lane >> 2);
            int col = col0 + wn * 64 + nt * 8 + (lane & 3) * 2;
            float bx = bias[col], by = bias[col + 1];
            float2 v0 = {acc[mt][nt][0] + bx, acc[mt][nt][1] + by};
            float2 v1 = {acc[mt][nt][2] + bx, acc[mt][nt][3] + by};
            *reinterpret_cast<float2*>(Cout + (size_t)row * Nt + col) = v0;
            *reinterpret_cast<float2*>(Cout + (size_t)(row + 8) * Nt + col) = v1;
        }
    }
}

// =================================================================
// fp32 -> (hi, lo) bf16 split, vectorized
// =================================================================
__global__ __launch_bounds__(256) void split_bf16_k(
    const float4* __restrict__ in, __nv_bfloat162* __restrict__ hi,
    __nv_bfloat162* __restrict__ lo, int n4)
{
    int i = blockIdx.x * blockDim.x + threadIdx.x;
    if (i >= n4) return;
    float4 a = in[i];
    uint32_t h0, l0, h1, l1;
    split_pack(a.x, a.y, h0, l0);
    split_pack(a.z, a.w, h1, l1);
    reinterpret_cast<uint32_t*>(hi)[2 * i]     = h0;
    reinterpret_cast<uint32_t*>(hi)[2 * i + 1] = h1;
    reinterpret_cast<uint32_t*>(lo)[2 * i]     = l0;
    reinterpret_cast<uint32_t*>(lo)[2 * i + 1] = l1;
}

// =================================================================
// RoPE + QK-RMSNorm -> Q,K bf16 hi/lo in [B,H,L,D]. Q pre-scaled 1/8.
// One warp per (b,l,h).
// =================================================================
__global__ __launch_bounds__(256) void rope_rms_split(
    const float* __restrict__ qkv,
    const float* __restrict__ q_gamma, const float* __restrict__ k_gamma,
    __nv_bfloat16* __restrict__ qh, __nv_bfloat16* __restrict__ ql,
    __nv_bfloat16* __restrict__ kh, __nv_bfloat16* __restrict__ kl)
{
    int warp = (blockIdx.x * blockDim.x + threadIdx.x) >> 5;
    int lane = threadIdx.x & 31;
    if (warp >= B_ * L_ * H_) return;
    int h  = warp % H_;
    int bl = warp / H_;
    int l  = bl % L_;
    int b  = bl / L_;

    const float* base = qkv + (size_t)bl * C3_;
    const size_t orow = (((size_t)(b * H_ + h)) * L_ + l) * D_ + 2 * lane;

    float inv_freq = exp2f((float)lane * (-13.287712379549449f / 32.0f));
    float ang = (float)l * inv_freq;
    float s, c;
    sincosf(ang, &s, &c);

    {
        float t1 = base[0 * C_ + h * D_ + 2 * lane];
        float t2 = base[0 * C_ + h * D_ + 2 * lane + 1];
        float r1 = t1 * c - t2 * s;
        float r2 = t1 * s + t2 * c;
        float ss = r1 * r1 + r2 * r2;
#pragma unroll
        for (int off = 16; off > 0; off >>= 1)
            ss += __shfl_xor_sync(0xffffffffu, ss, off);
        float inv = rsqrtf(ss * (1.0f / 64.0f) + 1e-6f) * 0.125f;
        float v0 = r1 * inv * q_gamma[h * D_ + 2 * lane];
        float v1 = r2 * inv * q_gamma[h * D_ + 2 * lane + 1];
        uint32_t hi, lo;
        split_pack(v0, v1, hi, lo);
        *reinterpret_cast<uint32_t*>(qh + orow) = hi;
        *reinterpret_cast<uint32_t*>(ql + orow) = lo;
    }
    {
        float t1 = base[1 * C_ + h * D_ + 2 * lane];
        float t2 = base[1 * C_ + h * D_ + 2 * lane + 1];
        float r1 = t1 * c - t2 * s;
        float r2 = t1 * s + t2 * c;
        float ss = r1 * r1 + r2 * r2;
#pragma unroll
        for (int off = 16; off > 0; off >>= 1)
            ss += __shfl_xor_sync(0xffffffffu, ss, off);
        float inv = rsqrtf(ss * (1.0f / 64.0f) + 1e-6f);
        float v0 = r1 * inv * k_gamma[h * D_ + 2 * lane];
        float v1 = r2 * inv * k_gamma[h * D_ + 2 * lane + 1];
        uint32_t hi, lo;
        split_pack(v0, v1, hi, lo);
        *reinterpret_cast<uint32_t*>(kh + orow) = hi;
        *reinterpret_cast<uint32_t*>(kl + orow) = lo;
    }
}

// =================================================================
// V transpose: g_qkv V-part [B,L,H,D] -> V^T bf16 hi/lo [B,H,D,L]
// =================================================================
__global__ __launch_bounds__(256) void v_transpose(
    const float* __restrict__ qkv,
    __nv_bfloat16* __restrict__ vth, __nv_bfloat16* __restrict__ vtl)
{
    __shared__ float ts[64][65];
    int tid = threadIdx.x;
    int l0 = blockIdx.x * 64;
    int bh = blockIdx.y;
    int b = bh >> 4, h = bh & 15;
    const float* src = qkv + (size_t)(b * L_ + l0) * C3_ + 2 * C_ + h * D_;
#pragma unroll
    for (int it = 0; it < 4; it++) {
        int lin = tid + it * 256;       // float4 index
        int i = lin >> 4, c4 = lin & 15;
        float4 v = *reinterpret_cast<const float4*>(src + (size_t)i * C3_ + c4 * 4);
        ts[i][c4 * 4 + 0] = v.x; ts[i][c4 * 4 + 1] = v.y;
        ts[i][c4 * 4 + 2] = v.z; ts[i][c4 * 4 + 3] = v.w;
    }
    __syncthreads();
#pragma unroll
    for (int it = 0; it < 8; it++) {
        int e2 = tid + it * 256;        // pair index
        int j = e2 >> 5, i = (e2 & 31) * 2;
        float a = ts[i][j], bb = ts[i + 1][j];
        uint32_t hi, lo;
        split_pack(a, bb, hi, lo);
        size_t idx = ((size_t)(bh * D_ + j)) * L_ + l0 + i;
        *reinterpret_cast<uint32_t*>(vth + idx) = hi;
        *reinterpret_cast<uint32_t*>(vtl + idx) = lo;
    }
}

// =================================================================
// Flash attention on mma.sync, split-bf16 for both S=QK^T and O=PV.
// Grid (L/128, H, B), 256 threads / 8 warps, 16 q-rows per warp.
// Smem: persistent Q hi/lo + double-buffered K/V^T hi/lo stages.
// =================================================================
#define AP       144                 // bytes per smem row (72 bf16)
#define Q_BYTES  (128 * AP)          // 18432
#define KV_MAT   (64 * AP)           // 9216
#define ASTG_SZ  (4 * KV_MAT)        // 36864
#define ATTN_DSMEM (2 * Q_BYTES + 2 * ASTG_SZ)   // 110592

__global__ __launch_bounds__(256, 2) void attn_mma(
    const __nv_bfloat16* __restrict__ qh_g, const __nv_bfloat16* __restrict__ ql_g,
    const __nv_bfloat16* __restrict__ kh_g, const __nv_bfloat16* __restrict__ kl_g,
    const __nv_bfloat16* __restrict__ vth_g, const __nv_bfloat16* __restrict__ vtl_g,
    __nv_bfloat16* __restrict__ ath, __nv_bfloat16* __restrict__ atl)
{
    extern __shared__ char dsm[];
    const uint32_t sb  = smem_u32(dsm);
    const uint32_t QHI = sb, QLO = sb + Q_BYTES, STG = sb + 2 * Q_BYTES;

    const int tid = threadIdx.x, wid = tid >> 5, lane = tid & 31;
    const int qt = blockIdx.x, h = blockIdx.y, b = blockIdx.z;
    const size_t base = ((size_t)(b * H_ + h)) * L_ * D_;  // same for q/k and v^T

    // Q tile (128 rows) hi/lo
#pragma unroll
    for (int it = 0; it < 4; it++) {
        int lin = tid + it * 256;
        int r = lin >> 3, c = lin & 7;
        uint32_t so = r * AP + c * 16;
        size_t go = base + (size_t)(qt * 128 + r) * D_ + c * 8;
        cpasync16(QHI + so, qh_g + go);
        cpasync16(QLO + so, ql_g + go);
    }
    asm volatile("cp.async.commit_group;" ::: "memory");

    auto load_kv = [&](int c, int s) {
        uint32_t st = STG + s * ASTG_SZ;
#pragma unroll
        for (int it = 0; it < 2; it++) {
            int lin = tid + it * 256;
            int r = lin >> 3, cc = lin & 7;
            uint32_t so = r * AP + cc * 16;
            size_t gk = base + (size_t)(c * 64 + r) * D_ + cc * 8;
            cpasync16(st + so,          kh_g + gk);
            cpasync16(st + KV_MAT + so, kl_g + gk);
            size_t gv = base + (size_t)r * L_ + c * 64 + cc * 8;
            cpasync16(st + 2 * KV_MAT + so, vth_g + gv);
            cpasync16(st + 3 * KV_MAT + so, vtl_g + gv);
        }
        asm volatile("cp.async.commit_group;" ::: "memory");
    };
    load_kv(0, 0);
    load_kv(1, 1);

    const int rlA = lane & 15;
    const int csA = (lane >> 4) << 3;
    const int rlB = (lane & 7) + ((lane >> 4) << 3);
    const int csB = lane & 8;

    float o[8][4];
#pragma unroll
    for (int j = 0; j < 8; j++)
#pragma unroll
        for (int t = 0; t < 4; t++) o[j][t] = 0.f;
    float m0 = -INFINITY, m1 = -INFINITY, l0 = 0.f, l1 = 0.f;

    const int NCH = L_ / 64;   // 32
    for (int c = 0; c < NCH; c++) {
        const int s = c & 1;
        if (c == NCH - 1)
            asm volatile("cp.async.wait_group 0;" ::: "memory");
        else
            asm volatile("cp.async.wait_group 1;" ::: "memory");
        __syncthreads();
        const uint32_t st = STG + s * ASTG_SZ;

        // ---- S = (Q*0.125) K^T, split-bf16 ----
        float sc[8][4];
#pragma unroll
        for (int j = 0; j < 8; j++)
#pragma unroll
            for (int t = 0; t < 4; t++) sc[j][t] = 0.f;
#pragma unroll
        for (int t = 0; t < 4; t++) {
            uint32_t qa = QHI + (uint32_t)((wid * 16 + rlA) * AP + (t * 16 + csA) * 2);
            uint32_t qhf[4], qlf[4];
            ldm4(qhf, qa);
            ldm4(qlf, qa + Q_BYTES);
#pragma unroll
            for (int p = 0; p < 4; p++) {
                uint32_t ka = st + (uint32_t)((p * 16 + rlB) * AP + (t * 16 + csB) * 2);
                uint32_t khf[4], klf[4];
                ldm4(khf, ka);
                ldm4(klf, ka + KV_MAT);
                mma_bf16(sc[2 * p],     qhf, khf);
                mma_bf16(sc[2 * p],     qhf, klf);
                mma_bf16(sc[2 * p],     qlf, khf);
                mma_bf16(sc[2 * p + 1], qhf, khf + 2);
                mma_bf16(sc[2 * p + 1], qhf, klf + 2);
                mma_bf16(sc[2 * p + 1], qlf, khf + 2);
            }
        }

        // ---- online softmax (rows r=lane>>2 and r+8, quad shuffles) ----
        float rm0 = -INFINITY, rm1 = -INFINITY;
#pragma unroll
        for (int j = 0; j < 8; j++) {
            rm0 = fmaxf(rm0, fmaxf(sc[j][0], sc[j][1]));
            rm1 = fmaxf(rm1, fmaxf(sc[j][2], sc[j][3]));
        }
        rm0 = fmaxf(rm0, __shfl_xor_sync(0xffffffffu, rm0, 1));
        rm0 = fmaxf(rm0, __shfl_xor_sync(0xffffffffu, rm0, 2));
        rm1 = fmaxf(rm1, __shfl_xor_sync(0xffffffffu, rm1, 1));
        rm1 = fmaxf(rm1, __shfl_xor_sync(0xffffffffu, rm1, 2));
        float n0 = fmaxf(m0, rm0), n1 = fmaxf(m1, rm1);
        float cr0 = __expf(m0 - n0), cr1 = __expf(m1 - n1);
        m0 = n0; m1 = n1;
        float s0 = 0.f, s1 = 0.f;
#pragma unroll
        for (int j = 0; j < 8; j++) {
            sc[j][0] = __expf(sc[j][0] - m0); s0 += sc[j][0];
            sc[j][1] = __expf(sc[j][1] - m0); s0 += sc[j][1];
            sc[j][2] = __expf(sc[j][2] - m1); s1 += sc[j][2];
            sc[j][3] = __expf(sc[j][3] - m1); s1 += sc[j][3];
        }
        s0 += __shfl_xor_sync(0xffffffffu, s0, 1);
        s0 += __shfl_xor_sync(0xffffffffu, s0, 2);
        s1 += __shfl_xor_sync(0xffffffffu, s1, 1);
        s1 += __shfl_xor_sync(0xffffffffu, s1, 2);
        l0 = l0 * cr0 + s0;
        l1 = l1 * cr1 + s1;
#pragma unroll
        for (int j = 0; j < 8; j++) {
            o[j][0] *= cr0; o[j][1] *= cr0;
            o[j][2] *= cr1; o[j][3] *= cr1;
        }

        // ---- O += P V, P from registers (split-bf16) ----
#pragma unroll
        for (int t = 0; t < 4; t++) {
            uint32_t pah[4], pal[4];
            split_pack(sc[2 * t][0],     sc[2 * t][1],     pah[0], pal[0]);
            split_pack(sc[2 * t][2],     sc[2 * t][3],     pah[1], pal[1]);
            split_pack(sc[2 * t + 1][0], sc[2 * t + 1][1], pah[2], pal[2]);
            split_pack(sc[2 * t + 1][2], sc[2 * t + 1][3], pah[3], pal[3]);
#pragma unroll
            for (int p = 0; p < 4; p++) {
                uint32_t va = st + 2 * KV_MAT
                            + (uint32_t)((p * 16 + rlB) * AP + (t * 16 + csB) * 2);
                uint32_t vhf[4], vlf[4];
                ldm4(vhf, va);
                ldm4(vlf, va + KV_MAT);
                mma_bf16(o[2 * p],     pah, vhf);
                mma_bf16(o[2 * p],     pah, vlf);
                mma_bf16(o[2 * p],     pal, vhf);
                mma_bf16(o[2 * p + 1], pah, vhf + 2);
                mma_bf16(o[2 * p + 1], pah, vlf + 2);
                mma_bf16(o[2 * p + 1], pal, vhf + 2);
            }
        }
        __syncthreads();
        if (c + 2 < NCH) load_kv(c + 2, s);
    }

    // ---- epilogue: normalize, split to bf16 hi/lo, write [B,L,C] ----
    float i0 = 1.f / l0, i1 = 1.f / l1;
    int ra = qt * 128 + wid * 16 + (lane >> 2);
    int colb = h * D_ + 2 * (lane & 3);
#pragma unroll
    for (int j = 0; j < 8; j++) {
        uint32_t h0, lo0, h1, lo1;
        split_pack(o[j][0] * i0, o[j][1] * i0, h0, lo0);
        split_pack(o[j][2] * i1, o[j][3] * i1, h1, lo1);
        size_t iA = (size_t)(b * L_ + ra) * C_ + colb + j * 8;
        size_t iB = iA + (size_t)8 * C_;
        *reinterpret_cast<uint32_t*>(ath + iA) = h0;
        *reinterpret_cast<uint32_t*>(atl + iA) = lo0;
        *reinterpret_cast<uint32_t*>(ath + iB) = h1;
        *reinterpret_cast<uint32_t*>(atl + iB) = lo1;
    }
}

// =================================================================
// Host launcher
// =================================================================
extern "C" void kernel_launch(void* const* d_in, const int* in_sizes, int n_in,
                              void* d_out, int out_size)
{
    const float* x       = (const float*)d_in[0];
    const float* w_qkv   = (const float*)d_in[1];
    const float* b_qkv   = (const float*)d_in[2];
    const float* w_out   = (const float*)d_in[3];
    const float* b_out   = (const float*)d_in[4];
    const float* q_gamma = (const float*)d_in[5];
    const float* k_gamma = (const float*)d_in[6];
    float* out = (float*)d_out;
    (void)in_sizes; (void)n_in; (void)out_size;

    float* qkv;
    __nv_bfloat16 *xhi, *xlo, *wqhi, *wqlo, *wohi, *wolo, *athi, *atlo;
    __nv_bfloat16 *qh, *ql, *kh, *kl, *vth, *vtl;
    cudaGetSymbolAddress((void**)&qkv,  g_qkv);
    cudaGetSymbolAddress((void**)&xhi,  g_x_hi);
    cudaGetSymbolAddress((void**)&xlo,  g_x_lo);
    cudaGetSymbolAddress((void**)&wqhi, g_wq_hi);
    cudaGetSymbolAddress((void**)&wqlo, g_wq_lo);
    cudaGetSymbolAddress((void**)&wohi, g_wo_hi);
    cudaGetSymbolAddress((void**)&wolo, g_wo_lo);
    cudaGetSymbolAddress((void**)&athi, g_at_hi);
    cudaGetSymbolAddress((void**)&atlo, g_at_lo);
    cudaGetSymbolAddress((void**)&qh,   g_qh);
    cudaGetSymbolAddress((void**)&ql,   g_ql);
    cudaGetSymbolAddress((void**)&kh,   g_kh);
    cudaGetSymbolAddress((void**)&kl,   g_kl);
    cudaGetSymbolAddress((void**)&vth,  g_vth);
    cudaGetSymbolAddress((void**)&vtl,  g_vtl);

    cudaFuncSetAttribute(gemm_mma,
                         cudaFuncAttributeMaxDynamicSharedMemorySize, GEMM_DSMEM);
    cudaFuncSetAttribute(attn_mma,
                         cudaFuncAttributeMaxDynamicSharedMemorySize, ATTN_DSMEM);

    // 0) split inputs/weights to bf16 hi/lo
    int n4;
    n4 = BL_ * C_ / 4;
    split_bf16_k<<<n4 / 256, 256>>>((const float4*)x,
        (__nv_bfloat162*)xhi, (__nv_bfloat162*)xlo, n4);
    n4 = C3_ * C_ / 4;
    split_bf16_k<<<n4 / 256, 256>>>((const float4*)w_qkv,
        (__nv_bfloat162*)wqhi, (__nv_bfloat162*)wqlo, n4);
    n4 = C_ * C_ / 4;
    split_bf16_k<<<n4 / 256, 256>>>((const float4*)w_out,
        (__nv_bfloat162*)wohi, (__nv_bfloat162*)wolo, n4);

    // 1) QKV projection
    gemm_mma<<<dim3(C3_ / 128, BL_ / 128), 256, GEMM_DSMEM>>>(
        xhi, xlo, wqhi, wqlo, b_qkv, qkv, C3_);

    // 2) RoPE + RMS -> Q,K bf16 hi/lo; V^T bf16 hi/lo
    rope_rms_split<<<(B_ * L_ * H_ * 32) / 256, 256>>>(qkv, q_gamma, k_gamma,
                                                       qh, ql, kh, kl);
    v_transpose<<<dim3(L_ / 64, B_ * H_), 256>>>(qkv, vth, vtl);

    // 3) Flash attention (tensor cores) -> att hi/lo bf16 [B,L,C]
    attn_mma<<<dim3(L_ / 128, H_, B_), 256, ATTN_DSMEM>>>(
        qh, ql, kh, kl, vth, vtl, athi, atlo);

    // 4) Output projection
    gemm_mma<<<dim3(C_ / 128, BL_ / 128), 256, GEMM_DSMEM>>>(
        athi, atlo, wohi, wolo, b_out, out, C_);
}

// round 10
// speedup vs baseline: 2.9315x; 1.0572x over previous
#include <cuda_runtime.h>
#include <cuda_bf16.h>
#include <math.h>
#include <stdint.h>

// Problem constants
#define B_  2
#define L_  2048
#define C_  1024
#define H_  16
#define D_  64
#define BL_ (B_*L_)      // 4096
#define C3_ (3*C_)       // 3072
#define K_  1024         // inner dim of both dense GEMMs

// ---------------- scratch (no allocation allowed) ----------------
__device__ float g_qkv[(size_t)BL_ * C3_];

__device__ __nv_bfloat16 g_x_hi [(size_t)BL_*C_];
__device__ __nv_bfloat16 g_x_lo [(size_t)BL_*C_];
__device__ __nv_bfloat16 g_wq_hi[(size_t)C3_*C_];
__device__ __nv_bfloat16 g_wq_lo[(size_t)C3_*C_];
__device__ __nv_bfloat16 g_wo_hi[(size_t)C_*C_];
__device__ __nv_bfloat16 g_wo_lo[(size_t)C_*C_];
__device__ __nv_bfloat16 g_at_hi[(size_t)BL_*C_];
__device__ __nv_bfloat16 g_at_lo[(size_t)BL_*C_];

__device__ __nv_bfloat16 g_qh [(size_t)B_*H_*L_*D_];
__device__ __nv_bfloat16 g_ql [(size_t)B_*H_*L_*D_];
__device__ __nv_bfloat16 g_kh [(size_t)B_*H_*L_*D_];
__device__ __nv_bfloat16 g_kl [(size_t)B_*H_*L_*D_];
__device__ __nv_bfloat16 g_vth[(size_t)B_*H_*D_*L_];
__device__ __nv_bfloat16 g_vtl[(size_t)B_*H_*D_*L_];

// =================================================================
// helpers
// =================================================================
__device__ __forceinline__ uint32_t smem_u32(const void* p) {
    uint32_t a;
    asm("{ .reg .u64 t; cvta.to.shared.u64 t, %1; cvt.u32.u64 %0, t; }"
        : "=r"(a) : "l"(p));
    return a;
}
__device__ __forceinline__ void cpasync16(uint32_t dst, const void* src) {
    asm volatile("cp.async.cg.shared.global [%0], [%1], 16;"
                 :: "r"(dst), "l"(src));
}
__device__ __forceinline__ void ldm4(uint32_t* r, uint32_t addr) {
    asm volatile("ldmatrix.sync.aligned.m8n8.x4.shared.b16 {%0,%1,%2,%3}, [%4];"
                 : "=r"(r[0]), "=r"(r[1]), "=r"(r[2]), "=r"(r[3]) : "r"(addr));
}
__device__ __forceinline__ void mma_bf16(float* c, const uint32_t* a,
                                         const uint32_t* b) {
    asm volatile(
        "mma.sync.aligned.m16n8k16.row.col.f32.bf16.bf16.f32 "
        "{%0,%1,%2,%3}, {%4,%5,%6,%7}, {%8,%9}, {%0,%1,%2,%3};"
        : "+f"(c[0]), "+f"(c[1]), "+f"(c[2]), "+f"(c[3])
        : "r"(a[0]), "r"(a[1]), "r"(a[2]), "r"(a[3]), "r"(b[0]), "r"(b[1]));
}
// pack two fp32 -> bf16x2 (e -> low half, o -> high half)
__device__ __forceinline__ uint32_t pack_bf16x2(float e, float o) {
    uint32_t r;
    asm("cvt.rn.bf16x2.f32 %0, %1, %2;" : "=r"(r) : "f"(o), "f"(e));
    return r;
}
// truncation split: hi = bf16-truncate(x) (exact in bf16), lo = x - hi
__device__ __forceinline__ void split_pack(float e, float o,
                                           uint32_t& hi, uint32_t& lo) {
    float he = __uint_as_float(__float_as_uint(e) & 0xffff0000u);
    float ho = __uint_as_float(__float_as_uint(o) & 0xffff0000u);
    hi = pack_bf16x2(he, ho);
    lo = pack_bf16x2(e - he, o - ho);
}

// =================================================================
// Split-bf16 mma.sync GEMM: C = A B^T + bias
// CTA 128x128, BK=32, 128 threads / 4 warps, warp tile 64x64.
// All fragments hoisted; MMAs issued term-major (reuse distance 32).
// =================================================================
#define PITCH_B   80
#define MAT_BYTES (128 * PITCH_B)
#define STG_BYTES (4 * MAT_BYTES)
#define GEMM_DSMEM (2 * STG_BYTES)

__global__ __launch_bounds__(128, 2)
void gemm_mma(const __nv_bfloat16* __restrict__ Ahi,
              const __nv_bfloat16* __restrict__ Alo,
              const __nv_bfloat16* __restrict__ Bhi,
              const __nv_bfloat16* __restrict__ Blo,
              const float* __restrict__ bias,
              float* __restrict__ Cout, int Nt)
{
    extern __shared__ char dsm[];
    const uint32_t sb = smem_u32(dsm);

    const int tid  = threadIdx.x;
    const int wid  = tid >> 5;
    const int lane = tid & 31;
    const int wm   = wid >> 1;        // 0..1 -> 64-row slab
    const int wn   = wid & 1;         // 0..1 -> 64-col slab
    const int row0 = blockIdx.y << 7;
    const int col0 = blockIdx.x << 7;

    auto load_chunk = [&](int c, int s) {
        const uint32_t st = sb + s * STG_BYTES;
        const int kb = c * 32;
#pragma unroll
        for (int t = 0; t < 4; t++) {       // A: 128 rows x 32 bf16
            int lin = tid + t * 128;
            int r = lin >> 2, q = lin & 3;
            uint32_t so = (uint32_t)(r * PITCH_B + q * 16);
            size_t go = (size_t)(row0 + r) * K_ + kb + q * 8;
            cpasync16(st + so,             Ahi + go);
            cpasync16(st + MAT_BYTES + so, Alo + go);
        }
#pragma unroll
        for (int t = 0; t < 4; t++) {       // B: 128 rows x 32 bf16
            int lin = tid + t * 128;
            int r = lin >> 2, q = lin & 3;
            uint32_t so = (uint32_t)(r * PITCH_B + q * 16);
            size_t go = (size_t)(col0 + r) * K_ + kb + q * 8;
            cpasync16(st + 2 * MAT_BYTES + so, Bhi + go);
            cpasync16(st + 3 * MAT_BYTES + so, Blo + go);
        }
        asm volatile("cp.async.commit_group;" ::: "memory");
    };

    float acc[4][8][4];
#pragma unroll
    for (int i = 0; i < 4; i++)
#pragma unroll
        for (int j = 0; j < 8; j++)
#pragma unroll
            for (int t = 0; t < 4; t++) acc[i][j][t] = 0.f;

    load_chunk(0, 0);
    load_chunk(1, 1);

    const int NCH = K_ / 32;          // 32
    const int rlA = lane & 15;
    const int csA = (lane >> 4) << 3;
    const int rlB = (lane & 7) + ((lane >> 4) << 3);
    const int csB = lane & 8;

    for (int c = 0; c < NCH; c++) {
        const int s = c & 1;
        if (c == NCH - 1)
            asm volatile("cp.async.wait_group 0;" ::: "memory");
        else
            asm volatile("cp.async.wait_group 1;" ::: "memory");
        __syncthreads();

        const uint32_t st = sb + s * STG_BYTES;
#pragma unroll
        for (int kk = 0; kk < 32; kk += 16) {
            uint32_t aH[4][4], aL[4][4], bH[4][4], bL[4][4];
#pragma unroll
            for (int mt = 0; mt < 4; mt++) {
                uint32_t ad = st + (uint32_t)((wm * 64 + mt * 16 + rlA) * PITCH_B
                                              + (kk + csA) * 2);
                ldm4(aH[mt], ad);
                ldm4(aL[mt], ad + MAT_BYTES);
            }
#pragma unroll
            for (int ntp = 0; ntp < 4; ntp++) {
                uint32_t bd = st + 2 * MAT_BYTES
                            + (uint32_t)((wn * 64 + ntp * 16 + rlB) * PITCH_B
                                         + (kk + csB) * 2);
                ldm4(bH[ntp], bd);
                ldm4(bL[ntp], bd + MAT_BYTES);
            }
            // term-major: same accumulator revisited only after 32 MMAs
#pragma unroll
            for (int mt = 0; mt < 4; mt++)
#pragma unroll
                for (int ntp = 0; ntp < 4; ntp++) {
                    mma_bf16(acc[mt][2 * ntp],     aH[mt], bH[ntp]);
                    mma_bf16(acc[mt][2 * ntp + 1], aH[mt], bH[ntp] + 2);
                }
#pragma unroll
            for (int mt = 0; mt < 4; mt++)
#pragma unroll
                for (int ntp = 0; ntp < 4; ntp++) {
                    mma_bf16(acc[mt][2 * ntp],     aH[mt], bL[ntp]);
                    mma_bf16(acc[mt][2 * ntp + 1], aH[mt], bL[ntp] + 2);
                }
#pragma unroll
            for (int mt = 0; mt < 4; mt++)
#pragma unroll
                for (int ntp = 0; ntp < 4; ntp++) {
                    mma_bf16(acc[mt][2 * ntp],     aL[mt], bH[ntp]);
                    mma_bf16(acc[mt][2 * ntp + 1], aL[mt], bH[ntp] + 2);
                }
        }
        __syncthreads();
        if (c + 2 < NCH) load_chunk(c + 2, s);
    }

    // Epilogue
#pragma unroll
    for (int mt = 0; mt < 4; mt++) {
#pragma unroll
        for (int nt = 0; nt < 8; nt++) {
            int row = row0 + wm * 64 + mt * 16 + (lane >> 2);
            int col = col0 + wn * 64 + nt * 8 + (lane & 3) * 2;
            float bx = bias[col], by = bias[col + 1];
            float2 v0 = {acc[mt][nt][0] + bx, acc[mt][nt][1] + by};
            float2 v1 = {acc[mt][nt][2] + bx, acc[mt][nt][3] + by};
            *reinterpret_cast<float2*>(Cout + (size_t)row * Nt + col) = v0;
            *reinterpret_cast<float2*>(Cout + (size_t)(row + 8) * Nt + col) = v1;
        }
    }
}

// =================================================================
// fp32 -> (hi, lo) bf16 split, vectorized
// =================================================================
__global__ __launch_bounds__(256) void split_bf16_k(
    const float4* __restrict__ in, __nv_bfloat162* __restrict__ hi,
    __nv_bfloat162* __restrict__ lo, int n4)
{
    int i = blockIdx.x * blockDim.x + threadIdx.x;
    if (i >= n4) return;
    float4 a = in[i];
    uint32_t h0, l0, h1, l1;
    split_pack(a.x, a.y, h0, l0);
    split_pack(a.z, a.w, h1, l1);
    reinterpret_cast<uint32_t*>(hi)[2 * i]     = h0;
    reinterpret_cast<uint32_t*>(hi)[2 * i + 1] = h1;
    reinterpret_cast<uint32_t*>(lo)[2 * i]     = l0;
    reinterpret_cast<uint32_t*>(lo)[2 * i + 1] = l1;
}

// =================================================================
// RoPE + QK-RMSNorm -> Q,K bf16 hi/lo in [B,H,L,D]. Q pre-scaled 1/8.
// =================================================================
__global__ __launch_bounds__(256) void rope_rms_split(
    const float* __restrict__ qkv,
    const float* __restrict__ q_gamma, const float* __restrict__ k_gamma,
    __nv_bfloat16* __restrict__ qh, __nv_bfloat16* __restrict__ ql,
    __nv_bfloat16* __restrict__ kh, __nv_bfloat16* __restrict__ kl)
{
    int warp = (blockIdx.x * blockDim.x + threadIdx.x) >> 5;
    int lane = threadIdx.x & 31;
    if (warp >= B_ * L_ * H_) return;
    int h  = warp % H_;
    int bl = warp / H_;
    int l  = bl % L_;
    int b  = bl / L_;

    const float* base = qkv + (size_t)bl * C3_;
    const size_t orow = (((size_t)(b * H_ + h)) * L_ + l) * D_ + 2 * lane;

    float inv_freq = exp2f((float)lane * (-13.287712379549449f / 32.0f));
    float ang = (float)l * inv_freq;
    float s, c;
    sincosf(ang, &s, &c);

    {
        float t1 = base[0 * C_ + h * D_ + 2 * lane];
        float t2 = base[0 * C_ + h * D_ + 2 * lane + 1];
        float r1 = t1 * c - t2 * s;
        float r2 = t1 * s + t2 * c;
        float ss = r1 * r1 + r2 * r2;
#pragma unroll
        for (int off = 16; off > 0; off >>= 1)
            ss += __shfl_xor_sync(0xffffffffu, ss, off);
        float inv = rsqrtf(ss * (1.0f / 64.0f) + 1e-6f) * 0.125f;
        float v0 = r1 * inv * q_gamma[h * D_ + 2 * lane];
        float v1 = r2 * inv * q_gamma[h * D_ + 2 * lane + 1];
        uint32_t hi, lo;
        split_pack(v0, v1, hi, lo);
        *reinterpret_cast<uint32_t*>(qh + orow) = hi;
        *reinterpret_cast<uint32_t*>(ql + orow) = lo;
    }
    {
        float t1 = base[1 * C_ + h * D_ + 2 * lane];
        float t2 = base[1 * C_ + h * D_ + 2 * lane + 1];
        float r1 = t1 * c - t2 * s;
        float r2 = t1 * s + t2 * c;
        float ss = r1 * r1 + r2 * r2;
#pragma unroll
        for (int off = 16; off > 0; off >>= 1)
            ss += __shfl_xor_sync(0xffffffffu, ss, off);
        float inv = rsqrtf(ss * (1.0f / 64.0f) + 1e-6f);
        float v0 = r1 * inv * k_gamma[h * D_ + 2 * lane];
        float v1 = r2 * inv * k_gamma[h * D_ + 2 * lane + 1];
        uint32_t hi, lo;
        split_pack(v0, v1, hi, lo);
        *reinterpret_cast<uint32_t*>(kh + orow) = hi;
        *reinterpret_cast<uint32_t*>(kl + orow) = lo;
    }
}

// =================================================================
// V transpose: g_qkv V-part [B,L,H,D] -> V^T bf16 hi/lo [B,H,D,L]
// =================================================================
__global__ __launch_bounds__(256) void v_transpose(
    const float* __restrict__ qkv,
    __nv_bfloat16* __restrict__ vth, __nv_bfloat16* __restrict__ vtl)
{
    __shared__ float ts[64][65];
    int tid = threadIdx.x;
    int l0 = blockIdx.x * 64;
    int bh = blockIdx.y;
    int b = bh >> 4, h = bh & 15;
    const float* src = qkv + (size_t)(b * L_ + l0) * C3_ + 2 * C_ + h * D_;
#pragma unroll
    for (int it = 0; it < 4; it++) {
        int lin = tid + it * 256;
        int i = lin >> 4, c4 = lin & 15;
        float4 v = *reinterpret_cast<const float4*>(src + (size_t)i * C3_ + c4 * 4);
        ts[i][c4 * 4 + 0] = v.x; ts[i][c4 * 4 + 1] = v.y;
        ts[i][c4 * 4 + 2] = v.z; ts[i][c4 * 4 + 3] = v.w;
    }
    __syncthreads();
#pragma unroll
    for (int it = 0; it < 8; it++) {
        int e2 = tid + it * 256;
        int j = e2 >> 5, i = (e2 & 31) * 2;
        float a = ts[i][j], bb = ts[i + 1][j];
        uint32_t hi, lo;
        split_pack(a, bb, hi, lo);
        size_t idx = ((size_t)(bh * D_ + j)) * L_ + l0 + i;
        *reinterpret_cast<uint32_t*>(vth + idx) = hi;
        *reinterpret_cast<uint32_t*>(vtl + idx) = lo;
    }
}

// =================================================================
// Flash attention on mma.sync, split-bf16 (unchanged from R9).
// =================================================================
#define AP       144
#define Q_BYTES  (128 * AP)
#define KV_MAT   (64 * AP)
#define ASTG_SZ  (4 * KV_MAT)
#define ATTN_DSMEM (2 * Q_BYTES + 2 * ASTG_SZ)

__global__ __launch_bounds__(256, 2) void attn_mma(
    const __nv_bfloat16* __restrict__ qh_g, const __nv_bfloat16* __restrict__ ql_g,
    const __nv_bfloat16* __restrict__ kh_g, const __nv_bfloat16* __restrict__ kl_g,
    const __nv_bfloat16* __restrict__ vth_g, const __nv_bfloat16* __restrict__ vtl_g,
    __nv_bfloat16* __restrict__ ath, __nv_bfloat16* __restrict__ atl)
{
    extern __shared__ char dsm[];
    const uint32_t sb  = smem_u32(dsm);
    const uint32_t QHI = sb, QLO = sb + Q_BYTES, STG = sb + 2 * Q_BYTES;

    const int tid = threadIdx.x, wid = tid >> 5, lane = tid & 31;
    const int qt = blockIdx.x, h = blockIdx.y, b = blockIdx.z;
    const size_t base = ((size_t)(b * H_ + h)) * L_ * D_;

#pragma unroll
    for (int it = 0; it < 4; it++) {
        int lin = tid + it * 256;
        int r = lin >> 3, c = lin & 7;
        uint32_t so = r * AP + c * 16;
        size_t go = base + (size_t)(qt * 128 + r) * D_ + c * 8;
        cpasync16(QHI + so, qh_g + go);
        cpasync16(QLO + so, ql_g + go);
    }
    asm volatile("cp.async.commit_group;" ::: "memory");

    auto load_kv = [&](int c, int s) {
        uint32_t st = STG + s * ASTG_SZ;
#pragma unroll
        for (int it = 0; it < 2; it++) {
            int lin = tid + it * 256;
            int r = lin >> 3, cc = lin & 7;
            uint32_t so = r * AP + cc * 16;
            size_t gk = base + (size_t)(c * 64 + r) * D_ + cc * 8;
            cpasync16(st + so,          kh_g + gk);
            cpasync16(st + KV_MAT + so, kl_g + gk);
            size_t gv = base + (size_t)r * L_ + c * 64 + cc * 8;
            cpasync16(st + 2 * KV_MAT + so, vth_g + gv);
            cpasync16(st + 3 * KV_MAT + so, vtl_g + gv);
        }
        asm volatile("cp.async.commit_group;" ::: "memory");
    };
    load_kv(0, 0);
    load_kv(1, 1);

    const int rlA = lane & 15;
    const int csA = (lane >> 4) << 3;
    const int rlB = (lane & 7) + ((lane >> 4) << 3);
    const int csB = lane & 8;

    float o[8][4];
#pragma unroll
    for (int j = 0; j < 8; j++)
#pragma unroll
        for (int t = 0; t < 4; t++) o[j][t] = 0.f;
    float m0 = -INFINITY, m1 = -INFINITY, l0 = 0.f, l1 = 0.f;

    const int NCH = L_ / 64;
    for (int c = 0; c < NCH; c++) {
        const int s = c & 1;
        if (c == NCH - 1)
            asm volatile("cp.async.wait_group 0;" ::: "memory");
        else
            asm volatile("cp.async.wait_group 1;" ::: "memory");
        __syncthreads();
        const uint32_t st = STG + s * ASTG_SZ;

        float sc[8][4];
#pragma unroll
        for (int j = 0; j < 8; j++)
#pragma unroll
            for (int t = 0; t < 4; t++) sc[j][t] = 0.f;
#pragma unroll
        for (int t = 0; t < 4; t++) {
            uint32_t qa = QHI + (uint32_t)((wid * 16 + rlA) * AP + (t * 16 + csA) * 2);
            uint32_t qhf[4], qlf[4];
            ldm4(qhf, qa);
            ldm4(qlf, qa + Q_BYTES);
#pragma unroll
            for (int p = 0; p < 4; p++) {
                uint32_t ka = st + (uint32_t)((p * 16 + rlB) * AP + (t * 16 + csB) * 2);
                uint32_t khf[4], klf[4];
                ldm4(khf, ka);
                ldm4(klf, ka + KV_MAT);
                mma_bf16(sc[2 * p],     qhf, khf);
                mma_bf16(sc[2 * p],     qhf, klf);
                mma_bf16(sc[2 * p],     qlf, khf);
                mma_bf16(sc[2 * p + 1], qhf, khf + 2);
                mma_bf16(sc[2 * p + 1], qhf, klf + 2);
                mma_bf16(sc[2 * p + 1], qlf, khf + 2);
            }
        }

        float rm0 = -INFINITY, rm1 = -INFINITY;
#pragma unroll
        for (int j = 0; j < 8; j++) {
            rm0 = fmaxf(rm0, fmaxf(sc[j][0], sc[j][1]));
            rm1 = fmaxf(rm1, fmaxf(sc[j][2], sc[j][3]));
        }
        rm0 = fmaxf(rm0, __shfl_xor_sync(0xffffffffu, rm0, 1));
        rm0 = fmaxf(rm0, __shfl_xor_sync(0xffffffffu, rm0, 2));
        rm1 = fmaxf(rm1, __shfl_xor_sync(0xffffffffu, rm1, 1));
        rm1 = fmaxf(rm1, __shfl_xor_sync(0xffffffffu, rm1, 2));
        float n0 = fmaxf(m0, rm0), n1 = fmaxf(m1, rm1);
        float cr0 = __expf(m0 - n0), cr1 = __expf(m1 - n1);
        m0 = n0; m1 = n1;
        float s0 = 0.f, s1 = 0.f;
#pragma unroll
        for (int j = 0; j < 8; j++) {
            sc[j][0] = __expf(sc[j][0] - m0); s0 += sc[j][0];
            sc[j][1] = __expf(sc[j][1] - m0); s0 += sc[j][1];
            sc[j][2] = __expf(sc[j][2] - m1); s1 += sc[j][2];
            sc[j][3] = __expf(sc[j][3] - m1); s1 += sc[j][3];
        }
        s0 += __shfl_xor_sync(0xffffffffu, s0, 1);
        s0 += __shfl_xor_sync(0xffffffffu, s0, 2);
        s1 += __shfl_xor_sync(0xffffffffu, s1, 1);
        s1 += __shfl_xor_sync(0xffffffffu, s1, 2);
        l0 = l0 * cr0 + s0;
        l1 = l1 * cr1 + s1;
#pragma unroll
        for (int j = 0; j < 8; j++) {
            o[j][0] *= cr0; o[j][1] *= cr0;
            o[j][2] *= cr1; o[j][3] *= cr1;
        }

#pragma unroll
        for (int t = 0; t < 4; t++) {
            uint32_t pah[4], pal[4];
            split_pack(sc[2 * t][0],     sc[2 * t][1],     pah[0], pal[0]);
            split_pack(sc[2 * t][2],     sc[2 * t][3],     pah[1], pal[1]);
            split_pack(sc[2 * t + 1][0], sc[2 * t + 1][1], pah[2], pal[2]);
            split_pack(sc[2 * t + 1][2], sc[2 * t + 1][3], pah[3], pal[3]);
#pragma unroll
            for (int p = 0; p < 4; p++) {
                uint32_t va = st + 2 * KV_MAT
                            + (uint32_t)((p * 16 + rlB) * AP + (t * 16 + csB) * 2);
                uint32_t vhf[4], vlf[4];
                ldm4(vhf, va);
                ldm4(vlf, va + KV_MAT);
                mma_bf16(o[2 * p],     pah, vhf);
                mma_bf16(o[2 * p],     pah, vlf);
                mma_bf16(o[2 * p],     pal, vhf);
                mma_bf16(o[2 * p + 1], pah, vhf + 2);
                mma_bf16(o[2 * p + 1], pah, vlf + 2);
                mma_bf16(o[2 * p + 1], pal, vhf + 2);
            }
        }
        __syncthreads();
        if (c + 2 < NCH) load_kv(c + 2, s);
    }

    float i0 = 1.f / l0, i1 = 1.f / l1;
    int ra = qt * 128 + wid * 16 + (lane >> 2);
    int colb = h * D_ + 2 * (lane & 3);
#pragma unroll
    for (int j = 0; j < 8; j++) {
        uint32_t h0, lo0, h1, lo1;
        split_pack(o[j][0] * i0, o[j][1] * i0, h0, lo0);
        split_pack(o[j][2] * i1, o[j][3] * i1, h1, lo1);
        size_t iA = (size_t)(b * L_ + ra) * C_ + colb + j * 8;
        size_t iB = iA + (size_t)8 * C_;
        *reinterpret_cast<uint32_t*>(ath + iA) = h0;
        *reinterpret_cast<uint32_t*>(atl + iA) = lo0;
        *reinterpret_cast<uint32_t*>(ath + iB) = h1;
        *reinterpret_cast<uint32_t*>(atl + iB) = lo1;
    }
}

// =================================================================
// Host launcher
// =================================================================
extern "C" void kernel_launch(void* const* d_in, const int* in_sizes, int n_in,
                              void* d_out, int out_size)
{
    const float* x       = (const float*)d_in[0];
    const float* w_qkv   = (const float*)d_in[1];
    const float* b_qkv   = (const float*)d_in[2];
    const float* w_out   = (const float*)d_in[3];
    const float* b_out   = (const float*)d_in[4];
    const float* q_gamma = (const float*)d_in[5];
    const float* k_gamma = (const float*)d_in[6];
    float* out = (float*)d_out;
    (void)in_sizes; (void)n_in; (void)out_size;

    float* qkv;
    __nv_bfloat16 *xhi, *xlo, *wqhi, *wqlo, *wohi, *wolo, *athi, *atlo;
    __nv_bfloat16 *qh, *ql, *kh, *kl, *vth, *vtl;
    cudaGetSymbolAddress((void**)&qkv,  g_qkv);
    cudaGetSymbolAddress((void**)&xhi,  g_x_hi);
    cudaGetSymbolAddress((void**)&xlo,  g_x_lo);
    cudaGetSymbolAddress((void**)&wqhi, g_wq_hi);
    cudaGetSymbolAddress((void**)&wqlo, g_wq_lo);
    cudaGetSymbolAddress((void**)&wohi, g_wo_hi);
    cudaGetSymbolAddress((void**)&wolo, g_wo_lo);
    cudaGetSymbolAddress((void**)&athi, g_at_hi);
    cudaGetSymbolAddress((void**)&atlo, g_at_lo);
    cudaGetSymbolAddress((void**)&qh,   g_qh);
    cudaGetSymbolAddress((void**)&ql,   g_ql);
    cudaGetSymbolAddress((void**)&kh,   g_kh);
    cudaGetSymbolAddress((void**)&kl,   g_kl);
    cudaGetSymbolAddress((void**)&vth,  g_vth);
    cudaGetSymbolAddress((void**)&vtl,  g_vtl);

    cudaFuncSetAttribute(gemm_mma,
                         cudaFuncAttributeMaxDynamicSharedMemorySize, GEMM_DSMEM);
    cudaFuncSetAttribute(attn_mma,
                         cudaFuncAttributeMaxDynamicSharedMemorySize, ATTN_DSMEM);

    // 0) split inputs/weights to bf16 hi/lo
    int n4;
    n4 = BL_ * C_ / 4;
    split_bf16_k<<<n4 / 256, 256>>>((const float4*)x,
        (__nv_bfloat162*)xhi, (__nv_bfloat162*)xlo, n4);
    n4 = C3_ * C_ / 4;
    split_bf16_k<<<n4 / 256, 256>>>((const float4*)w_qkv,
        (__nv_bfloat162*)wqhi, (__nv_bfloat162*)wqlo, n4);
    n4 = C_ * C_ / 4;
    split_bf16_k<<<n4 / 256, 256>>>((const float4*)w_out,
        (__nv_bfloat162*)wohi, (__nv_bfloat162*)wolo, n4);

    // 1) QKV projection
    gemm_mma<<<dim3(C3_ / 128, BL_ / 128), 128, GEMM_DSMEM>>>(
        xhi, xlo, wqhi, wqlo, b_qkv, qkv, C3_);

    // 2) RoPE + RMS -> Q,K bf16 hi/lo; V^T bf16 hi/lo
    rope_rms_split<<<(B_ * L_ * H_ * 32) / 256, 256>>>(qkv, q_gamma, k_gamma,
                                                       qh, ql, kh, kl);
    v_transpose<<<dim3(L_ / 64, B_ * H_), 256>>>(qkv, vth, vtl);

    // 3) Flash attention (tensor cores) -> att hi/lo bf16 [B,L,C]
    attn_mma<<<dim3(L_ / 128, H_, B_), 256, ATTN_DSMEM>>>(
        qh, ql, kh, kl, vth, vtl, athi, atlo);

    // 4) Output projection
    gemm_mma<<<dim3(C_ / 128, BL_ / 128), 128, GEMM_DSMEM>>>(
        athi, atlo, wohi, wolo, b_out, out, C_);
}